// round 1
// baseline (speedup 1.0000x reference)
#include <cuda_runtime.h>
#include <math.h>

#define BATCH 4
#define SEQ   1024
#define EMB   2048
#define NH    16
#define HD    128
#define MROWS (BATCH*SEQ)   /* 4096 */

// ---------------- scratch (device globals; no allocation allowed) ----------------
__device__ float g_Q[(size_t)64*1024*128];    // [B,H,S,D] 32MB
__device__ float g_K[(size_t)64*1024*128];
__device__ float g_V[(size_t)64*1024*128];
__device__ float g_ctx[(size_t)MROWS*EMB];    // [B,S,E]   32MB

// =================================================================================
// SGEMM: Y = X @ W^T.  X:[M,K] row-major, W:[N,K] row-major. M=4096,N=K=2048.
// BM=BN=128, BK=8, 256 threads, 8x8 per thread (split columns: n = 4tx+j and 64+4tx+j).
// mode 0: scatter into [B,H,S,D] scratch.  mode 1: plain [M,N] output.
// =================================================================================
__global__ __launch_bounds__(256)
void sgemm_xwt(const float* __restrict__ X, const float* __restrict__ W,
               float* __restrict__ Y, int mode)
{
    __shared__ __align__(16) float As[8][132];
    __shared__ __align__(16) float Bs[8][132];

    const int tid = threadIdx.x;
    const int m0 = blockIdx.y * 128;
    const int n0 = blockIdx.x * 128;
    const int ldRow = tid >> 1;          // 0..127
    const int ldK   = (tid & 1) * 4;     // 0 or 4
    const float* xPtr = X + (size_t)(m0 + ldRow) * EMB + ldK;
    const float* wPtr = W + (size_t)(n0 + ldRow) * EMB + ldK;
    const int tx = tid & 15;
    const int ty = tid >> 4;

    float acc[8][8];
#pragma unroll
    for (int i = 0; i < 8; ++i)
#pragma unroll
        for (int j = 0; j < 8; ++j) acc[i][j] = 0.0f;

    float4 xa = *(const float4*)xPtr;
    float4 wb = *(const float4*)wPtr;

    const int NT = EMB / 8;   // 256
    for (int t = 0; t < NT; ++t) {
        As[ldK+0][ldRow] = xa.x; As[ldK+1][ldRow] = xa.y;
        As[ldK+2][ldRow] = xa.z; As[ldK+3][ldRow] = xa.w;
        Bs[ldK+0][ldRow] = wb.x; Bs[ldK+1][ldRow] = wb.y;
        Bs[ldK+2][ldRow] = wb.z; Bs[ldK+3][ldRow] = wb.w;
        __syncthreads();
        if (t + 1 < NT) {
            xa = *(const float4*)(xPtr + (size_t)(t + 1) * 8);
            wb = *(const float4*)(wPtr + (size_t)(t + 1) * 8);
        }
#pragma unroll
        for (int kk = 0; kk < 8; ++kk) {
            float4 a0 = *(const float4*)&As[kk][ty*8];
            float4 a1 = *(const float4*)&As[kk][ty*8 + 4];
            float4 b0 = *(const float4*)&Bs[kk][tx*4];
            float4 b1 = *(const float4*)&Bs[kk][64 + tx*4];
            float av[8] = {a0.x,a0.y,a0.z,a0.w,a1.x,a1.y,a1.z,a1.w};
            float bv[8] = {b0.x,b0.y,b0.z,b0.w,b1.x,b1.y,b1.z,b1.w};
#pragma unroll
            for (int i = 0; i < 8; ++i)
#pragma unroll
                for (int j = 0; j < 8; ++j)
                    acc[i][j] += av[i] * bv[j];
        }
        __syncthreads();
    }

    if (mode == 0) {
        const int h = n0 >> 7;  // BN==HD: one head per block column
#pragma unroll
        for (int i = 0; i < 8; ++i) {
            int m = m0 + ty*8 + i;
            int b = m >> 10, s2 = m & 1023;
            float* row = Y + (((size_t)(b*NH + h)) * SEQ + s2) * HD;
            *(float4*)(row + tx*4)      = make_float4(acc[i][0],acc[i][1],acc[i][2],acc[i][3]);
            *(float4*)(row + 64 + tx*4) = make_float4(acc[i][4],acc[i][5],acc[i][6],acc[i][7]);
        }
    } else {
#pragma unroll
        for (int i = 0; i < 8; ++i) {
            int m = m0 + ty*8 + i;
            float* row = Y + (size_t)m * EMB + n0;
            *(float4*)(row + tx*4)      = make_float4(acc[i][0],acc[i][1],acc[i][2],acc[i][3]);
            *(float4*)(row + 64 + tx*4) = make_float4(acc[i][4],acc[i][5],acc[i][6],acc[i][7]);
        }
    }
}

// =================================================================================
// RoPE in place on Q and K, layout [B,H,S,D]. cos/sin: [S,D], halves identical.
// out[d]    = x[d]*c - x[d+64]*s
// out[d+64] = x[d+64]*c + x[d]*s
// =================================================================================
__global__ __launch_bounds__(256)
void rope_kernel(float* __restrict__ Q, float* __restrict__ K,
                 const float* __restrict__ cosT, const float* __restrict__ sinT)
{
    int idx = blockIdx.x * 256 + threadIdx.x;          // BH*S*64 total
    int d  = idx & 63;
    int s2 = (idx >> 6) & 1023;
    int bh = idx >> 16;
    size_t base = ((size_t)bh * SEQ + s2) * HD;
    float c  = cosT[s2*HD + d];
    float sn = sinT[s2*HD + d];

    float q1 = Q[base + d], q2 = Q[base + d + 64];
    Q[base + d]      = q1*c - q2*sn;
    Q[base + d + 64] = q2*c + q1*sn;

    float k1 = K[base + d], k2 = K[base + d + 64];
    K[base + d]      = k1*c - k2*sn;
    K[base + d + 64] = k2*c + k1*sn;
}

// =================================================================================
// Flash attention, fp32, causal. Grid: (qt=8, bh=64). 512 threads.
// Q tile 128 rows, K/V tile 64 rows. Online softmax. Writes ctx in [B,S,E].
// smem (floats): Qs[128][132] | Kst[128][68] (K transposed) | Vs[64][132] | Ps[128][68]
// =================================================================================
#define SM_QS  0
#define SM_KST 16896
#define SM_VS  25600
#define SM_PS  34048
#define ATTN_SMEM_BYTES (42752 * 4)   /* 171008 B */

__global__ __launch_bounds__(512)
void attn_kernel(const float* __restrict__ Q, const float* __restrict__ K,
                 const float* __restrict__ V, float* __restrict__ ctx)
{
    extern __shared__ __align__(16) float sm[];
    float* Qs  = sm + SM_QS;
    float* Kst = sm + SM_KST;
    float* Vs  = sm + SM_VS;
    float* Ps  = sm + SM_PS;

    const int bh = blockIdx.y;
    const int qt = blockIdx.x;
    const int q0 = qt * 128;
    const int tid = threadIdx.x;
    const int tx = tid & 15;
    const int ty = tid >> 4;          // 0..31
    const float scale = 0.08838834764831845f;   // 1/sqrt(128)

    // load Q tile (pre-scaled)
    const float* Qg = Q + ((size_t)bh * SEQ + q0) * HD;
    for (int f = tid; f < (128*128)/4; f += 512) {
        int row = f >> 5;
        int col = (f & 31) << 2;
        float4 v = *(const float4*)(Qg + row*HD + col);
        v.x *= scale; v.y *= scale; v.z *= scale; v.w *= scale;
        *(float4*)&Qs[row*132 + col] = v;
    }

    float acc[4][8];
    float mrow[4], lrow[4];
#pragma unroll
    for (int i = 0; i < 4; ++i) {
        mrow[i] = -1e30f; lrow[i] = 0.0f;
#pragma unroll
        for (int j = 0; j < 8; ++j) acc[i][j] = 0.0f;
    }

    const int nfull = q0 >> 6;        // tiles < nfull need no mask
    const int ktmax = nfull + 1;      // inclusive

    for (int kt = 0; kt <= ktmax; ++kt) {
        __syncthreads();   // prev PV done (also orders Q-tile load on iter 0)
        const float* Kg = K + ((size_t)bh * SEQ + kt*64) * HD;
        const float* Vg = V + ((size_t)bh * SEQ + kt*64) * HD;
        for (int f = tid; f < (64*128)/4; f += 512) {
            int row = f >> 5;
            int col = (f & 31) << 2;
            float4 kv = *(const float4*)(Kg + row*HD + col);
            Kst[(col+0)*68 + row] = kv.x;
            Kst[(col+1)*68 + row] = kv.y;
            Kst[(col+2)*68 + row] = kv.z;
            Kst[(col+3)*68 + row] = kv.w;
            float4 vv = *(const float4*)(Vg + row*HD + col);
            *(float4*)&Vs[row*132 + col] = vv;
        }
        __syncthreads();

        // S = (Q*scale) K^T   (thread: rows ty*4+i, cols tx*4+jj)
        float s[4][4];
#pragma unroll
        for (int i = 0; i < 4; ++i)
#pragma unroll
            for (int j = 0; j < 4; ++j) s[i][j] = 0.0f;

        for (int d = 0; d < HD; d += 4) {
            float4 kb0 = *(const float4*)&Kst[(d+0)*68 + tx*4];
            float4 kb1 = *(const float4*)&Kst[(d+1)*68 + tx*4];
            float4 kb2 = *(const float4*)&Kst[(d+2)*68 + tx*4];
            float4 kb3 = *(const float4*)&Kst[(d+3)*68 + tx*4];
#pragma unroll
            for (int i = 0; i < 4; ++i) {
                float4 qa = *(const float4*)&Qs[(ty*4+i)*132 + d];
                s[i][0] += qa.x*kb0.x + qa.y*kb1.x + qa.z*kb2.x + qa.w*kb3.x;
                s[i][1] += qa.x*kb0.y + qa.y*kb1.y + qa.z*kb2.y + qa.w*kb3.y;
                s[i][2] += qa.x*kb0.z + qa.y*kb1.z + qa.z*kb2.z + qa.w*kb3.z;
                s[i][3] += qa.x*kb0.w + qa.y*kb1.w + qa.z*kb2.w + qa.w*kb3.w;
            }
        }

        if (kt >= nfull) {   // causal mask on the two diagonal tiles
#pragma unroll
            for (int i = 0; i < 4; ++i) {
                int qg = q0 + ty*4 + i;
#pragma unroll
                for (int jj = 0; jj < 4; ++jj) {
                    int kg = kt*64 + tx*4 + jj;
                    if (kg > qg) s[i][jj] = -1e30f;
                }
            }
        }

        // online softmax (row group = 16 lanes sharing ty)
#pragma unroll
        for (int i = 0; i < 4; ++i) {
            float tm = fmaxf(fmaxf(s[i][0], s[i][1]), fmaxf(s[i][2], s[i][3]));
#pragma unroll
            for (int o = 8; o > 0; o >>= 1)
                tm = fmaxf(tm, __shfl_xor_sync(0xffffffffu, tm, o));
            float mnew = fmaxf(mrow[i], tm);
            float alpha = __expf(mrow[i] - mnew);
            mrow[i] = mnew;
            float p0 = __expf(s[i][0] - mnew);
            float p1 = __expf(s[i][1] - mnew);
            float p2 = __expf(s[i][2] - mnew);
            float p3 = __expf(s[i][3] - mnew);
            float ts = (p0 + p1) + (p2 + p3);
#pragma unroll
            for (int o = 8; o > 0; o >>= 1)
                ts += __shfl_xor_sync(0xffffffffu, ts, o);
            lrow[i] = lrow[i] * alpha + ts;
#pragma unroll
            for (int j = 0; j < 8; ++j) acc[i][j] *= alpha;
            *(float4*)&Ps[(ty*4+i)*68 + tx*4] = make_float4(p0, p1, p2, p3);
        }
        __syncthreads();

        // O += P @ V   (thread cols: 4tx+j and 64+4tx+j)
        for (int sc = 0; sc < 64; ++sc) {
            float4 v1 = *(const float4*)&Vs[sc*132 + tx*4];
            float4 v2 = *(const float4*)&Vs[sc*132 + 64 + tx*4];
#pragma unroll
            for (int i = 0; i < 4; ++i) {
                float pa = Ps[(ty*4+i)*68 + sc];
                acc[i][0] += pa*v1.x; acc[i][1] += pa*v1.y;
                acc[i][2] += pa*v1.z; acc[i][3] += pa*v1.w;
                acc[i][4] += pa*v2.x; acc[i][5] += pa*v2.y;
                acc[i][6] += pa*v2.z; acc[i][7] += pa*v2.w;
            }
        }
    }

    const int b = bh >> 4, h = bh & 15;
#pragma unroll
    for (int i = 0; i < 4; ++i) {
        int q = q0 + ty*4 + i;
        float inv = 1.0f / lrow[i];
        float* row = ctx + ((size_t)(b*SEQ + q)) * EMB + h*HD;
        *(float4*)(row + tx*4) =
            make_float4(acc[i][0]*inv, acc[i][1]*inv, acc[i][2]*inv, acc[i][3]*inv);
        *(float4*)(row + 64 + tx*4) =
            make_float4(acc[i][4]*inv, acc[i][5]*inv, acc[i][6]*inv, acc[i][7]*inv);
    }
}

// =================================================================================
extern "C" void kernel_launch(void* const* d_in, const int* in_sizes, int n_in,
                              void* d_out, int out_size)
{
    const float* query = (const float*)d_in[0];
    const float* key   = (const float*)d_in[1];
    const float* value = (const float*)d_in[2];
    /* d_in[3] = mask (causal, implicit) */
    const float* cosT  = (const float*)d_in[4];
    const float* sinT  = (const float*)d_in[5];
    const float* Wq    = (const float*)d_in[6];
    const float* Wk    = (const float*)d_in[7];
    const float* Wv    = (const float*)d_in[8];
    const float* Wo    = (const float*)d_in[9];

    float *pQ, *pK, *pV, *pC;
    cudaGetSymbolAddress((void**)&pQ, g_Q);
    cudaGetSymbolAddress((void**)&pK, g_K);
    cudaGetSymbolAddress((void**)&pV, g_V);
    cudaGetSymbolAddress((void**)&pC, g_ctx);

    dim3 gGemm(EMB/128, MROWS/128);   // (16, 32)

    sgemm_xwt<<<gGemm, 256>>>(query, Wq, pQ, 0);
    sgemm_xwt<<<gGemm, 256>>>(key,   Wk, pK, 0);
    sgemm_xwt<<<gGemm, 256>>>(value, Wv, pV, 0);

    rope_kernel<<<(64*1024*64)/256, 256>>>(pQ, pK, cosT, sinT);

    cudaFuncSetAttribute(attn_kernel,
                         cudaFuncAttributeMaxDynamicSharedMemorySize,
                         ATTN_SMEM_BYTES);
    attn_kernel<<<dim3(8, 64), 512, ATTN_SMEM_BYTES>>>(pQ, pK, pV, pC);

    sgemm_xwt<<<gGemm, 256>>>(pC, Wo, (float*)d_out, 1);
}

// round 3
// speedup vs baseline: 1.8167x; 1.8167x over previous
#include <cuda_runtime.h>
#include <cuda_bf16.h>
#include <math.h>
#include <stdint.h>

#define BATCH 4
#define SEQ   1024
#define EMB   2048
#define NH    16
#define HD    128
#define MROWS (BATCH*SEQ)   /* 4096 */

// ---------------- scratch (device globals; no allocation allowed) ----------------
__device__ float g_Q[(size_t)64*1024*128];    // [B,H,S,D]
__device__ float g_K[(size_t)64*1024*128];
__device__ float g_V[(size_t)64*1024*128];
__device__ float g_ctx[(size_t)MROWS*EMB];    // [B,S,E]
__device__ __nv_bfloat16 g_Xh[(size_t)MROWS*EMB];
__device__ __nv_bfloat16 g_Xl[(size_t)MROWS*EMB];
__device__ __nv_bfloat16 g_Wh[(size_t)EMB*EMB];
__device__ __nv_bfloat16 g_Wl[(size_t)EMB*EMB];

// ======================= portable PTX helpers (sm_80+) ===========================
__device__ __forceinline__ uint32_t smem_u32(const void* p) {
    uint32_t a;
    asm("{ .reg .u64 t; cvta.to.shared.u64 t, %1; cvt.u32.u64 %0, t; }" : "=r"(a) : "l"(p));
    return a;
}
#define CP_ASYNC16(dst, src) \
    asm volatile("cp.async.cg.shared.global [%0], [%1], 16;" :: "r"(dst), "l"(src) : "memory")
#define CP_COMMIT()   asm volatile("cp.async.commit_group;" ::: "memory")
#define CP_WAIT2()    asm volatile("cp.async.wait_group 2;" ::: "memory")

__device__ __forceinline__ void ldsm_x4(uint32_t& r0, uint32_t& r1, uint32_t& r2,
                                        uint32_t& r3, uint32_t addr) {
    asm volatile("ldmatrix.sync.aligned.m8n8.x4.shared.b16 {%0,%1,%2,%3}, [%4];"
                 : "=r"(r0), "=r"(r1), "=r"(r2), "=r"(r3) : "r"(addr));
}
__device__ __forceinline__ void mma16816(float* d, const uint32_t* a, const uint32_t* b) {
    asm volatile("mma.sync.aligned.m16n8k16.row.col.f32.bf16.bf16.f32 "
                 "{%0,%1,%2,%3}, {%4,%5,%6,%7}, {%8,%9}, {%0,%1,%2,%3};"
                 : "+f"(d[0]), "+f"(d[1]), "+f"(d[2]), "+f"(d[3])
                 : "r"(a[0]), "r"(a[1]), "r"(a[2]), "r"(a[3]), "r"(b[0]), "r"(b[1]));
}
// 64B rows, 16B chunks; swizzle keeps 8x8 ldmatrix (8 rows x 16B) conflict-free.
__device__ __forceinline__ uint32_t swz64(int row, int colByte) {
    return (uint32_t)(row * 64 + ((((colByte >> 4) ^ (row >> 1)) & 3) * 16));
}

// ======================= split fp32 -> bf16 hi/lo ================================
__global__ __launch_bounds__(256)
void split_bf16(const float* __restrict__ X, __nv_bfloat16* __restrict__ Hi,
                __nv_bfloat16* __restrict__ Lo, int n4)
{
    int i = blockIdx.x * 256 + threadIdx.x;
    if (i >= n4) return;
    float4 v = ((const float4*)X)[i];
    __nv_bfloat16 h0 = __float2bfloat16(v.x);
    __nv_bfloat16 h1 = __float2bfloat16(v.y);
    __nv_bfloat16 h2 = __float2bfloat16(v.z);
    __nv_bfloat16 h3 = __float2bfloat16(v.w);
    __nv_bfloat16 l0 = __float2bfloat16(v.x - __bfloat162float(h0));
    __nv_bfloat16 l1 = __float2bfloat16(v.y - __bfloat162float(h1));
    __nv_bfloat16 l2 = __float2bfloat16(v.z - __bfloat162float(h2));
    __nv_bfloat16 l3 = __float2bfloat16(v.w - __bfloat162float(h3));
    __nv_bfloat162* H2 = (__nv_bfloat162*)Hi;
    __nv_bfloat162* L2 = (__nv_bfloat162*)Lo;
    H2[2*i]   = __nv_bfloat162(h0, h1);
    H2[2*i+1] = __nv_bfloat162(h2, h3);
    L2[2*i]   = __nv_bfloat162(l0, l1);
    L2[2*i+1] = __nv_bfloat162(l2, l3);
}

// ======================= mma.sync split-bf16 GEMM ================================
// Y[M,N] = (Ah+Al)[M,K] @ (Bh+Bl)[N,K]^T  (drop Al*Bl), fp32 accum in registers.
// CTA 128x256, BK=32, 512 threads (16 warps, warp tile 32x64), 3-stage cp.async.
// mode 0: scatter to [B,H,S,D]; mode 1: plain [M,EMB].
#define GBM 128
#define GBN 256
#define GBK 32
#define OFF_AH 0
#define OFF_AL 8192
#define OFF_BH 16384
#define OFF_BL 32768
#define STAGE_BYTES 49152
#define GEMM_SMEM (3 * STAGE_BYTES)   /* 147456 */

__global__ __launch_bounds__(512, 1)
void gemm_split_mma(const __nv_bfloat16* __restrict__ Ah, const __nv_bfloat16* __restrict__ Al,
                    const __nv_bfloat16* __restrict__ Bh, const __nv_bfloat16* __restrict__ Bl,
                    float* __restrict__ Y, int mode)
{
    extern __shared__ __align__(128) char smc[];
    const uint32_t sb = smem_u32(smc);
    const int tid = threadIdx.x, lane = tid & 31, wid = tid >> 5;
    const int m0 = blockIdx.y * GBM, n0 = blockIdx.x * GBN;
    const int warp_m = wid & 3;    // 4 groups x 32 rows
    const int warp_n = wid >> 2;   // 4 groups x 64 cols

    float acc[2][8][4];
#pragma unroll
    for (int i = 0; i < 2; ++i)
#pragma unroll
        for (int j = 0; j < 8; ++j)
#pragma unroll
            for (int r = 0; r < 4; ++r) acc[i][j][r] = 0.0f;

    // ---- tile-load issue for chunk c into stage c%3 ----
    auto issue_stage = [&](int c) {
        const uint32_t st = sb + (uint32_t)(c % 3) * STAGE_BYTES;
        const int kc = c * GBK;
        // 3072 16B chunks: Ah[0,512) Al[512,1024) Bh[1024,2048) Bl[2048,3072)
#pragma unroll
        for (int u = 0; u < 6; ++u) {
            int f = tid + u * 512;
            uint32_t dst; const __nv_bfloat16* gp;
            if (f < 1024) {
                int rel = f & 511;
                int row = rel >> 2, ch = rel & 3;
                const __nv_bfloat16* base = (f < 512) ? Ah : Al;
                gp  = base + (size_t)(m0 + row) * EMB + kc + ch * 8;
                dst = st + ((f < 512) ? OFF_AH : OFF_AL) + swz64(row, ch * 16);
            } else {
                int rel = (f - 1024) & 1023;
                int row = rel >> 2, ch = rel & 3;
                const __nv_bfloat16* base = (f < 2048) ? Bh : Bl;
                gp  = base + (size_t)(n0 + row) * EMB + kc + ch * 8;
                dst = st + ((f < 2048) ? OFF_BH : OFF_BL) + swz64(row, ch * 16);
            }
            CP_ASYNC16(dst, gp);
        }
        CP_COMMIT();
    };

    issue_stage(0); issue_stage(1); issue_stage(2);

    // ldmatrix per-lane bases
    const int a_row = warp_m * 32 + ((lane >> 3) & 1) * 8 + (lane & 7);  // + i*16
    const int a_cb  = (lane >> 4) * 16;                                   // + ks*32
    const int b_row = warp_n * 64 + ((lane >> 4) & 1) * 8 + (lane & 7);  // + q*16
    const int b_cb  = ((lane >> 3) & 1) * 16;                             // + ks*32

    const int NC = EMB / GBK;   // 64
    for (int c = 0; c < NC; ++c) {
        CP_WAIT2();
        __syncthreads();
        const uint32_t st = sb + (uint32_t)(c % 3) * STAGE_BYTES;

#pragma unroll
        for (int ks = 0; ks < 2; ++ks) {
            const int cb = ks * 32;
            uint32_t a[2][2][4];   // [split][mfrag][4]
#pragma unroll
            for (int i = 0; i < 2; ++i) {
                ldsm_x4(a[0][i][0], a[0][i][1], a[0][i][2], a[0][i][3],
                        st + OFF_AH + swz64(a_row + i * 16, a_cb + cb));
                ldsm_x4(a[1][i][0], a[1][i][1], a[1][i][2], a[1][i][3],
                        st + OFF_AL + swz64(a_row + i * 16, a_cb + cb));
            }
            uint32_t b[8][2];
            // Bh: AhBh + AlBh
#pragma unroll
            for (int q = 0; q < 4; ++q)
                ldsm_x4(b[2*q][0], b[2*q][1], b[2*q+1][0], b[2*q+1][1],
                        st + OFF_BH + swz64(b_row + q * 16, b_cb + cb));
#pragma unroll
            for (int i = 0; i < 2; ++i)
#pragma unroll
                for (int j = 0; j < 8; ++j) {
                    mma16816(acc[i][j], a[0][i], b[j]);
                    mma16816(acc[i][j], a[1][i], b[j]);
                }
            // Bl: AhBl
#pragma unroll
            for (int q = 0; q < 4; ++q)
                ldsm_x4(b[2*q][0], b[2*q][1], b[2*q+1][0], b[2*q+1][1],
                        st + OFF_BL + swz64(b_row + q * 16, b_cb + cb));
#pragma unroll
            for (int i = 0; i < 2; ++i)
#pragma unroll
                for (int j = 0; j < 8; ++j)
                    mma16816(acc[i][j], a[0][i], b[j]);
        }

        __syncthreads();
        if (c + 3 < NC) issue_stage(c + 3);
        else CP_COMMIT();   // keep group accounting aligned for CP_WAIT2
    }

    // ---- epilogue: write fp32 ----
    const int r0q = lane >> 2, c0q = (lane & 3) * 2;
#pragma unroll
    for (int i = 0; i < 2; ++i) {
#pragma unroll
        for (int j = 0; j < 8; ++j) {
            int mrow0 = m0 + warp_m * 32 + i * 16 + r0q;
            int ncol  = n0 + warp_n * 64 + j * 8 + c0q;
            float* p0; float* p1;
            if (mode == 0) {
                int h = ncol >> 7, dc = ncol & 127;
                int b0 = mrow0 >> 10, s0 = mrow0 & 1023;
                int b1 = (mrow0 + 8) >> 10, s1 = (mrow0 + 8) & 1023;
                p0 = Y + (((size_t)(b0 * NH + h)) * SEQ + s0) * HD + dc;
                p1 = Y + (((size_t)(b1 * NH + h)) * SEQ + s1) * HD + dc;
            } else {
                p0 = Y + (size_t)mrow0 * EMB + ncol;
                p1 = Y + (size_t)(mrow0 + 8) * EMB + ncol;
            }
            *(float2*)p0 = make_float2(acc[i][j][0], acc[i][j][1]);
            *(float2*)p1 = make_float2(acc[i][j][2], acc[i][j][3]);
        }
    }
}

// =================================================================================
// RoPE in place on Q and K, layout [B,H,S,D].
// =================================================================================
__global__ __launch_bounds__(256)
void rope_kernel(float* __restrict__ Q, float* __restrict__ K,
                 const float* __restrict__ cosT, const float* __restrict__ sinT)
{
    int idx = blockIdx.x * 256 + threadIdx.x;
    int d  = idx & 63;
    int s2 = (idx >> 6) & 1023;
    int bh = idx >> 16;
    size_t base = ((size_t)bh * SEQ + s2) * HD;
    float c  = cosT[s2*HD + d];
    float sn = sinT[s2*HD + d];
    float q1 = Q[base + d], q2 = Q[base + d + 64];
    Q[base + d]      = q1*c - q2*sn;
    Q[base + d + 64] = q2*c + q1*sn;
    float k1 = K[base + d], k2 = K[base + d + 64];
    K[base + d]      = k1*c - k2*sn;
    K[base + d + 64] = k2*c + k1*sn;
}

// =================================================================================
// Flash attention, fp32, causal (R1 passing version).
// =================================================================================
#define SM_QS  0
#define SM_KST 16896
#define SM_VS  25600
#define SM_PS  34048
#define ATTN_SMEM_BYTES (42752 * 4)

__global__ __launch_bounds__(512)
void attn_kernel(const float* __restrict__ Q, const float* __restrict__ K,
                 const float* __restrict__ V, float* __restrict__ ctx)
{
    extern __shared__ __align__(16) float smf[];
    float* Qs  = smf + SM_QS;
    float* Kst = smf + SM_KST;
    float* Vs  = smf + SM_VS;
    float* Ps  = smf + SM_PS;

    const int bh = blockIdx.y;
    const int qt = blockIdx.x;
    const int q0 = qt * 128;
    const int tid = threadIdx.x;
    const int tx = tid & 15;
    const int ty = tid >> 4;
    const float scale = 0.08838834764831845f;

    const float* Qg = Q + ((size_t)bh * SEQ + q0) * HD;
    for (int f = tid; f < (128*128)/4; f += 512) {
        int row = f >> 5;
        int col = (f & 31) << 2;
        float4 v = *(const float4*)(Qg + row*HD + col);
        v.x *= scale; v.y *= scale; v.z *= scale; v.w *= scale;
        *(float4*)&Qs[row*132 + col] = v;
    }

    float acc[4][8];
    float mrow[4], lrow[4];
#pragma unroll
    for (int i = 0; i < 4; ++i) {
        mrow[i] = -1e30f; lrow[i] = 0.0f;
#pragma unroll
        for (int j = 0; j < 8; ++j) acc[i][j] = 0.0f;
    }

    const int nfull = q0 >> 6;
    const int ktmax = nfull + 1;

    for (int kt = 0; kt <= ktmax; ++kt) {
        __syncthreads();
        const float* Kg = K + ((size_t)bh * SEQ + kt*64) * HD;
        const float* Vg = V + ((size_t)bh * SEQ + kt*64) * HD;
        for (int f = tid; f < (64*128)/4; f += 512) {
            int row = f >> 5;
            int col = (f & 31) << 2;
            float4 kv = *(const float4*)(Kg + row*HD + col);
            Kst[(col+0)*68 + row] = kv.x;
            Kst[(col+1)*68 + row] = kv.y;
            Kst[(col+2)*68 + row] = kv.z;
            Kst[(col+3)*68 + row] = kv.w;
            float4 vv = *(const float4*)(Vg + row*HD + col);
            *(float4*)&Vs[row*132 + col] = vv;
        }
        __syncthreads();

        float s[4][4];
#pragma unroll
        for (int i = 0; i < 4; ++i)
#pragma unroll
            for (int j = 0; j < 4; ++j) s[i][j] = 0.0f;

        for (int d = 0; d < HD; d += 4) {
            float4 kb0 = *(const float4*)&Kst[(d+0)*68 + tx*4];
            float4 kb1 = *(const float4*)&Kst[(d+1)*68 + tx*4];
            float4 kb2 = *(const float4*)&Kst[(d+2)*68 + tx*4];
            float4 kb3 = *(const float4*)&Kst[(d+3)*68 + tx*4];
#pragma unroll
            for (int i = 0; i < 4; ++i) {
                float4 qa = *(const float4*)&Qs[(ty*4+i)*132 + d];
                s[i][0] += qa.x*kb0.x + qa.y*kb1.x + qa.z*kb2.x + qa.w*kb3.x;
                s[i][1] += qa.x*kb0.y + qa.y*kb1.y + qa.z*kb2.y + qa.w*kb3.y;
                s[i][2] += qa.x*kb0.z + qa.y*kb1.z + qa.z*kb2.z + qa.w*kb3.z;
                s[i][3] += qa.x*kb0.w + qa.y*kb1.w + qa.z*kb2.w + qa.w*kb3.w;
            }
        }

        if (kt >= nfull) {
#pragma unroll
            for (int i = 0; i < 4; ++i) {
                int qg = q0 + ty*4 + i;
#pragma unroll
                for (int jj = 0; jj < 4; ++jj) {
                    int kg = kt*64 + tx*4 + jj;
                    if (kg > qg) s[i][jj] = -1e30f;
                }
            }
        }

#pragma unroll
        for (int i = 0; i < 4; ++i) {
            float tm = fmaxf(fmaxf(s[i][0], s[i][1]), fmaxf(s[i][2], s[i][3]));
#pragma unroll
            for (int o = 8; o > 0; o >>= 1)
                tm = fmaxf(tm, __shfl_xor_sync(0xffffffffu, tm, o));
            float mnew = fmaxf(mrow[i], tm);
            float alpha = __expf(mrow[i] - mnew);
            mrow[i] = mnew;
            float p0 = __expf(s[i][0] - mnew);
            float p1 = __expf(s[i][1] - mnew);
            float p2 = __expf(s[i][2] - mnew);
            float p3 = __expf(s[i][3] - mnew);
            float ts = (p0 + p1) + (p2 + p3);
#pragma unroll
            for (int o = 8; o > 0; o >>= 1)
                ts += __shfl_xor_sync(0xffffffffu, ts, o);
            lrow[i] = lrow[i] * alpha + ts;
#pragma unroll
            for (int j = 0; j < 8; ++j) acc[i][j] *= alpha;
            *(float4*)&Ps[(ty*4+i)*68 + tx*4] = make_float4(p0, p1, p2, p3);
        }
        __syncthreads();

        for (int sc = 0; sc < 64; ++sc) {
            float4 v1 = *(const float4*)&Vs[sc*132 + tx*4];
            float4 v2 = *(const float4*)&Vs[sc*132 + 64 + tx*4];
#pragma unroll
            for (int i = 0; i < 4; ++i) {
                float pa = Ps[(ty*4+i)*68 + sc];
                acc[i][0] += pa*v1.x; acc[i][1] += pa*v1.y;
                acc[i][2] += pa*v1.z; acc[i][3] += pa*v1.w;
                acc[i][4] += pa*v2.x; acc[i][5] += pa*v2.y;
                acc[i][6] += pa*v2.z; acc[i][7] += pa*v2.w;
            }
        }
    }

    const int b = bh >> 4, h = bh & 15;
#pragma unroll
    for (int i = 0; i < 4; ++i) {
        int q = q0 + ty*4 + i;
        float inv = 1.0f / lrow[i];
        float* row = ctx + ((size_t)(b*SEQ + q)) * EMB + h*HD;
        *(float4*)(row + tx*4) =
            make_float4(acc[i][0]*inv, acc[i][1]*inv, acc[i][2]*inv, acc[i][3]*inv);
        *(float4*)(row + 64 + tx*4) =
            make_float4(acc[i][4]*inv, acc[i][5]*inv, acc[i][6]*inv, acc[i][7]*inv);
    }
}

// =================================================================================
extern "C" void kernel_launch(void* const* d_in, const int* in_sizes, int n_in,
                              void* d_out, int out_size)
{
    const float* query = (const float*)d_in[0];
    const float* key   = (const float*)d_in[1];
    const float* value = (const float*)d_in[2];
    const float* cosT  = (const float*)d_in[4];
    const float* sinT  = (const float*)d_in[5];
    const float* Wq    = (const float*)d_in[6];
    const float* Wk    = (const float*)d_in[7];
    const float* Wv    = (const float*)d_in[8];
    const float* Wo    = (const float*)d_in[9];

    float *pQ, *pK, *pV, *pC;
    __nv_bfloat16 *pXh, *pXl, *pWh, *pWl;
    cudaGetSymbolAddress((void**)&pQ,  g_Q);
    cudaGetSymbolAddress((void**)&pK,  g_K);
    cudaGetSymbolAddress((void**)&pV,  g_V);
    cudaGetSymbolAddress((void**)&pC,  g_ctx);
    cudaGetSymbolAddress((void**)&pXh, g_Xh);
    cudaGetSymbolAddress((void**)&pXl, g_Xl);
    cudaGetSymbolAddress((void**)&pWh, g_Wh);
    cudaGetSymbolAddress((void**)&pWl, g_Wl);

    cudaFuncSetAttribute(gemm_split_mma, cudaFuncAttributeMaxDynamicSharedMemorySize,
                         GEMM_SMEM);
    cudaFuncSetAttribute(attn_kernel, cudaFuncAttributeMaxDynamicSharedMemorySize,
                         ATTN_SMEM_BYTES);

    const int nX4 = MROWS * EMB / 4;
    const int nW4 = EMB * EMB / 4;
    dim3 gGemm(EMB / GBN, MROWS / GBM);   // (8, 32)

    // Q projection
    split_bf16<<<nX4/256, 256>>>(query, pXh, pXl, nX4);
    split_bf16<<<nW4/256, 256>>>(Wq, pWh, pWl, nW4);
    gemm_split_mma<<<gGemm, 512, GEMM_SMEM>>>(pXh, pXl, pWh, pWl, pQ, 0);
    // K projection
    split_bf16<<<nX4/256, 256>>>(key, pXh, pXl, nX4);
    split_bf16<<<nW4/256, 256>>>(Wk, pWh, pWl, nW4);
    gemm_split_mma<<<gGemm, 512, GEMM_SMEM>>>(pXh, pXl, pWh, pWl, pK, 0);
    // V projection
    split_bf16<<<nX4/256, 256>>>(value, pXh, pXl, nX4);
    split_bf16<<<nW4/256, 256>>>(Wv, pWh, pWl, nW4);
    gemm_split_mma<<<gGemm, 512, GEMM_SMEM>>>(pXh, pXl, pWh, pWl, pV, 0);

    rope_kernel<<<(64*1024*64)/256, 256>>>(pQ, pK, cosT, sinT);

    attn_kernel<<<dim3(8, 64), 512, ATTN_SMEM_BYTES>>>(pQ, pK, pV, pC);

    // output projection
    split_bf16<<<nX4/256, 256>>>(pC, pXh, pXl, nX4);
    split_bf16<<<nW4/256, 256>>>(Wo, pWh, pWl, nW4);
    gemm_split_mma<<<gGemm, 512, GEMM_SMEM>>>(pXh, pXl, pWh, pWl, (float*)d_out, 1);
}